// round 2
// baseline (speedup 1.0000x reference)
#include <cuda_runtime.h>
#include <math.h>

#define Dd 1024
#define Mm 8192
#define Hh 16
#define Bb 64
#define HDd 64

// ---------------- scratch (device globals; no allocation allowed) ----------
__device__ float g_q[Bb * Dd];
__device__ float g_qh[Bb * Dd];
__device__ float g_Wck[Dd * Dd];
__device__ float g_Wcv[Dd * Dd];
__device__ float g_bck[Dd];
__device__ float g_bcv[Dd];
__device__ float g_kh[Mm * Dd];
__device__ float g_vh[Mm * Dd];
__device__ float g_scores[Bb * Hh * Mm];
__device__ float g_ctx[Bb * Dd];
__device__ float g_ms[Bb * Dd];
__device__ float g_gin[Bb * 2 * Dd];
__device__ float g_g1[Bb * Dd];
__device__ float g_gated[Bb * Dd];
__device__ float g_comb[Bb * 2 * Dd];
__device__ float g_i1[Bb * 2 * Dd];

// ---------------- generic tiled SGEMM --------------------------------------
// TN mode (NN_MODE=false): C[m,n] = sum_k A[m,k] * B[n,k]    (B is N x K row-major)
// NN mode (NN_MODE=true):  C[m,n] = sum_k A[m,k] * B[k,n]    (B is K x N row-major)
// Batched via blockIdx.z = batch * nsplit + split. Split-K accumulates with atomics.
// Epilogue: v = alpha*acc (+bias[n]) -> act(0 none,1 relu,2 sigmoid) -> (*mul[m,n])
template <int BM, int BN, int BK, int TM, int TN, bool NN_MODE, bool ATOMIC>
__global__ void __launch_bounds__(256) gemm_k(
    const float* __restrict__ A, const float* __restrict__ Bm, float* __restrict__ C,
    int Mdim, int Ndim, int Kdim,
    int lda, int ldb, int ldc,
    int sA, int sB, int sC,
    int nsplit, float alpha,
    const float* __restrict__ bias, int act, const float* __restrict__ mul)
{
    constexpr int TX = BN / TN;
    constexpr int TY = BM / TM;
    static_assert(TX * TY == 256, "256 threads");

    __shared__ float As[BK * BM];
    __shared__ float Bs[BK * BN];

    const int tid = threadIdx.x;
    const int tx = tid % TX;
    const int ty = tid / TX;

    const int z = blockIdx.z;
    const int batch = z / nsplit;
    const int split = z % nsplit;
    A += batch * sA;
    Bm += batch * sB;
    C += batch * sC;

    const int Ks = Kdim / nsplit;
    int k0 = split * Ks;
    const int kend = k0 + Ks;

    const int m0 = blockIdx.y * BM;
    const int n0 = blockIdx.x * BN;

    float acc[TM][TN];
#pragma unroll
    for (int i = 0; i < TM; i++)
#pragma unroll
        for (int j = 0; j < TN; j++) acc[i][j] = 0.0f;

    constexpr int AK4 = BK / 4;           // float4 chunks per A row
    const int aRow = tid / AK4;
    const int aC4 = (tid % AK4) * 4;

    for (; k0 < kend; k0 += BK) {
        // ---- load A tile (BM x BK), store transposed As[k][m]
        {
            float4 av = *(const float4*)&A[(m0 + aRow) * lda + k0 + aC4];
            As[(aC4 + 0) * BM + aRow] = av.x;
            As[(aC4 + 1) * BM + aRow] = av.y;
            As[(aC4 + 2) * BM + aRow] = av.z;
            As[(aC4 + 3) * BM + aRow] = av.w;
        }
        // ---- load B tile
        if (NN_MODE) {
            constexpr int BN4 = BN / 4;
            const int bK = tid / BN4;
            const int bC = (tid % BN4) * 4;
            float4 bv = *(const float4*)&Bm[(k0 + bK) * ldb + n0 + bC];
            *(float4*)&Bs[bK * BN + bC] = bv;
        } else {
            const int bRow = tid / AK4;
            const int bC4 = (tid % AK4) * 4;
            float4 bv = *(const float4*)&Bm[(n0 + bRow) * ldb + k0 + bC4];
            Bs[(bC4 + 0) * BN + bRow] = bv.x;
            Bs[(bC4 + 1) * BN + bRow] = bv.y;
            Bs[(bC4 + 2) * BN + bRow] = bv.z;
            Bs[(bC4 + 3) * BN + bRow] = bv.w;
        }
        __syncthreads();

#pragma unroll
        for (int k = 0; k < BK; k++) {
            float ar[TM], br[TN];
#pragma unroll
            for (int i = 0; i < TM; i += 4)
                *(float4*)&ar[i] = *(const float4*)&As[k * BM + ty * TM + i];
#pragma unroll
            for (int j = 0; j < TN; j += 4)
                *(float4*)&br[j] = *(const float4*)&Bs[k * BN + tx * TN + j];
#pragma unroll
            for (int i = 0; i < TM; i++)
#pragma unroll
                for (int j = 0; j < TN; j++) acc[i][j] = fmaf(ar[i], br[j], acc[i][j]);
        }
        __syncthreads();
    }

    // ---- epilogue
#pragma unroll
    for (int i = 0; i < TM; i++) {
        const int r = m0 + ty * TM + i;
#pragma unroll
        for (int j = 0; j < TN; j++) {
            const int c = n0 + tx * TN + j;
            float v = acc[i][j] * alpha;
            if (ATOMIC) {
                atomicAdd(&C[r * ldc + c], v);
            } else {
                if (bias) v += bias[c];
                if (act == 1) v = fmaxf(v, 0.0f);
                else if (act == 2) v = 1.0f / (1.0f + expf(-v));
                if (mul) v *= mul[r * ldc + c];
                C[r * ldc + c] = v;
            }
        }
    }
}

// ---------------- small helper kernels -------------------------------------
// out[row] = b2[row] + dot(W[row,:], b1)   (rows = Dd)
__global__ void bias_combine_k(const float* __restrict__ W, const float* __restrict__ b1,
                               const float* __restrict__ b2, float* __restrict__ out)
{
    const int row = blockIdx.x * blockDim.y + threadIdx.y;
    const int lane = threadIdx.x;
    float s = 0.0f;
    for (int c = lane; c < Dd; c += 32) s += W[row * Dd + c] * b1[c];
#pragma unroll
    for (int o = 16; o; o >>= 1) s += __shfl_down_sync(0xffffffffu, s, o);
    if (lane == 0) out[row] = s + b2[row];
}

__global__ void zero_k(float* p, int n)
{
    const int i = blockIdx.x * 256 + threadIdx.x;
    if (i < n) p[i] = 0.0f;
}

// o[B x 2D] = concat(a[B x D], b[B x D])
__global__ void concat_k(const float* __restrict__ a, const float* __restrict__ b,
                         float* __restrict__ o)
{
    const int i = blockIdx.x * 256 + threadIdx.x;
    if (i >= Bb * 2 * Dd) return;
    const int r = i / (2 * Dd);
    const int c = i % (2 * Dd);
    o[i] = (c < Dd) ? a[r * Dd + c] : b[r * Dd + c - Dd];
}

// in-place softmax over rows of length Mm; grid = B*H rows
__global__ void softmax_k(float* __restrict__ s)
{
    float* row = s + (size_t)blockIdx.x * Mm;
    __shared__ float red[256];
    const int t = threadIdx.x;

    float mx = -1e30f;
    for (int i = t; i < Mm; i += 256) mx = fmaxf(mx, row[i]);
    red[t] = mx;
    __syncthreads();
    for (int o = 128; o; o >>= 1) {
        if (t < o) red[t] = fmaxf(red[t], red[t + o]);
        __syncthreads();
    }
    mx = red[0];
    __syncthreads();

    float sum = 0.0f;
    for (int i = t; i < Mm; i += 256) {
        float e = expf(row[i] - mx);
        row[i] = e;
        sum += e;
    }
    red[t] = sum;
    __syncthreads();
    for (int o = 128; o; o >>= 1) {
        if (t < o) red[t] += red[t + o];
        __syncthreads();
    }
    const float inv = 1.0f / red[0];
    for (int i = t; i < Mm; i += 256) row[i] *= inv;
}

// ---------------- launch ----------------------------------------------------
extern "C" void kernel_launch(void* const* d_in, const int* in_sizes, int n_in,
                              void* d_out, int out_size)
{
    (void)in_sizes; (void)n_in; (void)out_size;
    const float* x    = (const float*)d_in[0];
    const float* mk   = (const float*)d_in[1];
    const float* mv   = (const float*)d_in[2];
    const float* Wq   = (const float*)d_in[3];
    const float* bq   = (const float*)d_in[4];
    const float* Wk   = (const float*)d_in[5];
    const float* bk   = (const float*)d_in[6];
    const float* Wv   = (const float*)d_in[7];
    const float* bv   = (const float*)d_in[8];
    const float* ipw  = (const float*)d_in[9];   // (3D, D)
    const float* ipb  = (const float*)d_in[10];  // (3D,)
    const float* outw = (const float*)d_in[11];
    const float* outb = (const float*)d_in[12];
    const float* gW1  = (const float*)d_in[13];  // (D, 2D)
    const float* gb1  = (const float*)d_in[14];
    const float* gW2  = (const float*)d_in[15];
    const float* gb2  = (const float*)d_in[16];
    const float* iW1  = (const float*)d_in[17];  // (2D, 2D)
    const float* ib1  = (const float*)d_in[18];
    const float* iW2  = (const float*)d_in[19];  // (D, 2D)
    const float* ib2  = (const float*)d_in[20];
    float* out = (float*)d_out;

    const float* Wiq = ipw;
    const float* Wik = ipw + Dd * Dd;
    const float* Wiv = ipw + 2 * Dd * Dd;
    const float* biq = ipb;
    const float* bik = ipb + Dd;
    const float* biv = ipb + 2 * Dd;

    // resolve device-global addresses (host side; not an allocation)
    float *q, *qh, *Wck, *Wcv, *bck, *bcv, *kh, *vh, *scores, *ctx, *ms, *gin, *g1, *gated, *comb, *i1;
    cudaGetSymbolAddress((void**)&q, g_q);
    cudaGetSymbolAddress((void**)&qh, g_qh);
    cudaGetSymbolAddress((void**)&Wck, g_Wck);
    cudaGetSymbolAddress((void**)&Wcv, g_Wcv);
    cudaGetSymbolAddress((void**)&bck, g_bck);
    cudaGetSymbolAddress((void**)&bcv, g_bcv);
    cudaGetSymbolAddress((void**)&kh, g_kh);
    cudaGetSymbolAddress((void**)&vh, g_vh);
    cudaGetSymbolAddress((void**)&scores, g_scores);
    cudaGetSymbolAddress((void**)&ctx, g_ctx);
    cudaGetSymbolAddress((void**)&ms, g_ms);
    cudaGetSymbolAddress((void**)&gin, g_gin);
    cudaGetSymbolAddress((void**)&g1, g_g1);
    cudaGetSymbolAddress((void**)&gated, g_gated);
    cudaGetSymbolAddress((void**)&comb, g_comb);
    cudaGetSymbolAddress((void**)&i1, g_i1);

    const dim3 blk(256);

    // 1) combined biases: bck = bik + Wik@bk ; bcv = biv + Wiv@bv
    bias_combine_k<<<Dd / 8, dim3(32, 8)>>>(Wik, bk, bik, bck);
    bias_combine_k<<<Dd / 8, dim3(32, 8)>>>(Wiv, bv, biv, bcv);

    // 2) combined weights: Wck = Wik @ Wk, Wcv = Wiv @ Wv   (NN, 1024^3)
    gemm_k<128, 128, 8, 8, 8, true, false><<<dim3(8, 8, 1), blk>>>(
        Wik, Wk, Wck, Dd, Dd, Dd, Dd, Dd, Dd, 0, 0, 0, 1, 1.0f, nullptr, 0, nullptr);
    gemm_k<128, 128, 8, 8, 8, true, false><<<dim3(8, 8, 1), blk>>>(
        Wiv, Wv, Wcv, Dd, Dd, Dd, Dd, Dd, Dd, 0, 0, 0, 1, 1.0f, nullptr, 0, nullptr);

    // 3) kh = keys @ Wck^T + bck ; vh = values @ Wcv^T + bcv   (TN, 8192x1024x1024)
    gemm_k<128, 128, 8, 8, 8, false, false><<<dim3(8, 64, 1), blk>>>(
        mk, Wck, kh, Mm, Dd, Dd, Dd, Dd, Dd, 0, 0, 0, 1, 1.0f, bck, 0, nullptr);
    gemm_k<128, 128, 8, 8, 8, false, false><<<dim3(8, 64, 1), blk>>>(
        mv, Wcv, vh, Mm, Dd, Dd, Dd, Dd, Dd, 0, 0, 0, 1, 1.0f, bcv, 0, nullptr);

    // 4) q = x @ Wq^T + bq ; qh = q @ Wiq^T + biq   (TN small)
    gemm_k<64, 64, 16, 4, 4, false, false><<<dim3(16, 1, 1), blk>>>(
        x, Wq, q, Bb, Dd, Dd, Dd, Dd, Dd, 0, 0, 0, 1, 1.0f, bq, 0, nullptr);
    gemm_k<64, 64, 16, 4, 4, false, false><<<dim3(16, 1, 1), blk>>>(
        q, Wiq, qh, Bb, Dd, Dd, Dd, Dd, Dd, 0, 0, 0, 1, 1.0f, biq, 0, nullptr);

    // 5) scores[b,h,m] = 0.125 * sum_d qh[b,h*64+d]*kh[m,h*64+d]   (batched TN per head)
    gemm_k<64, 64, 16, 4, 4, false, false><<<dim3(Mm / 64, 1, Hh), blk>>>(
        qh, kh, scores, Bb, Mm, HDd, Dd, Dd, Hh * Mm, HDd, HDd, Mm,
        1, 0.125f, nullptr, 0, nullptr);

    // 6) softmax over m
    softmax_k<<<Bb * Hh, blk>>>(scores);

    // 7) ctx = attn @ vh   (batched NN per head, split-K=8, atomic accumulate)
    zero_k<<<(Bb * Dd + 255) / 256, blk>>>(ctx, Bb * Dd);
    gemm_k<64, 64, 16, 4, 4, true, true><<<dim3(1, 1, Hh * 8), blk>>>(
        scores, vh, ctx, Bb, HDd, Mm, Hh * Mm, Dd, Dd, Mm, HDd, HDd,
        8, 1.0f, nullptr, 0, nullptr);

    // 8) memory_signal = ctx @ out_w^T + out_b
    gemm_k<64, 64, 16, 4, 4, false, false><<<dim3(16, 1, 1), blk>>>(
        ctx, outw, ms, Bb, Dd, Dd, Dd, Dd, Dd, 0, 0, 0, 1, 1.0f, outb, 0, nullptr);

    // 9) gate path: gin = [x, ms]; g1 = relu(gin@gW1^T+gb1); gated = sigmoid(g1@gW2^T+gb2)*ms
    concat_k<<<(Bb * 2 * Dd + 255) / 256, blk>>>(x, ms, gin);
    gemm_k<64, 64, 16, 4, 4, false, false><<<dim3(16, 1, 1), blk>>>(
        gin, gW1, g1, Bb, Dd, 2 * Dd, 2 * Dd, 2 * Dd, Dd, 0, 0, 0, 1, 1.0f, gb1, 1, nullptr);
    gemm_k<64, 64, 16, 4, 4, false, false><<<dim3(16, 1, 1), blk>>>(
        g1, gW2, gated, Bb, Dd, Dd, Dd, Dd, Dd, 0, 0, 0, 1, 1.0f, gb2, 2, ms);

    // 10) output path: comb = [x, gated]; i1 = relu(comb@iW1^T+ib1); out = i1@iW2^T+ib2
    concat_k<<<(Bb * 2 * Dd + 255) / 256, blk>>>(x, gated, comb);
    gemm_k<64, 64, 16, 4, 4, false, false><<<dim3(32, 1, 1), blk>>>(
        comb, iW1, i1, Bb, 2 * Dd, 2 * Dd, 2 * Dd, 2 * Dd, 2 * Dd, 0, 0, 0, 1, 1.0f, ib1, 1, nullptr);
    gemm_k<64, 64, 16, 4, 4, false, false><<<dim3(16, 1, 1), blk>>>(
        i1, iW2, out, Bb, Dd, 2 * Dd, 2 * Dd, 2 * Dd, Dd, 0, 0, 0, 1, 1.0f, ib2, 0, nullptr);
}

// round 3
// speedup vs baseline: 1.0059x; 1.0059x over previous
#include <cuda_runtime.h>
#include <math.h>

#define Dd 1024
#define Mm 8192
#define Hh 16
#define Bb 64
#define HDd 64

// ---------------- scratch (device globals; no allocation allowed) ----------
__device__ float g_q[Bb * Dd];
__device__ float g_qh[Bb * Dd];
__device__ float g_Wck[Dd * Dd];
__device__ float g_Wcv[Dd * Dd];
__device__ float g_bck[Dd];
__device__ float g_bcv[Dd];
__device__ float g_kh[Mm * Dd];
__device__ float g_vh[Mm * Dd];
__device__ float g_scores[Bb * Hh * Mm];
__device__ float g_ctx[Bb * Dd];
__device__ float g_ms[Bb * Dd];
__device__ float g_gin[Bb * 2 * Dd];
__device__ float g_g1[Bb * Dd];
__device__ float g_gated[Bb * Dd];
__device__ float g_comb[Bb * 2 * Dd];
__device__ float g_i1[Bb * 2 * Dd];

// ---------------- generic tiled SGEMM --------------------------------------
// TN mode (NN_MODE=false): C[m,n] = sum_k A[m,k] * B[n,k]    (B is N x K row-major)
// NN mode (NN_MODE=true):  C[m,n] = sum_k A[m,k] * B[k,n]    (B is K x N row-major)
// Batched via blockIdx.z = batch * nsplit + split. Split-K accumulates with atomics.
// Epilogue: v = alpha*acc (+bias[n]) -> act(0 none,1 relu,2 sigmoid) -> (*mul[m,n])
template <int BM, int BN, int BK, int TM, int TN, bool NN_MODE, bool ATOMIC>
__global__ void __launch_bounds__(256) gemm_k(
    const float* __restrict__ A, const float* __restrict__ Bm, float* __restrict__ C,
    int Mdim, int Ndim, int Kdim,
    int lda, int ldb, int ldc,
    int sA, int sB, int sC,
    int nsplit, float alpha,
    const float* __restrict__ bias, int act, const float* __restrict__ mul)
{
    constexpr int TX = BN / TN;
    constexpr int TY = BM / TM;
    static_assert(TX * TY == 256, "256 threads");

    __shared__ float As[BK * BM];
    __shared__ float Bs[BK * BN];

    const int tid = threadIdx.x;
    const int tx = tid % TX;
    const int ty = tid / TX;

    const int z = blockIdx.z;
    const int batch = z / nsplit;
    const int split = z % nsplit;
    A += batch * sA;
    Bm += batch * sB;
    C += batch * sC;

    const int Ks = Kdim / nsplit;
    int k0 = split * Ks;
    const int kend = k0 + Ks;

    const int m0 = blockIdx.y * BM;
    const int n0 = blockIdx.x * BN;

    float acc[TM][TN];
#pragma unroll
    for (int i = 0; i < TM; i++)
#pragma unroll
        for (int j = 0; j < TN; j++) acc[i][j] = 0.0f;

    constexpr int AK4 = BK / 4;           // float4 chunks per A row
    const int aRow = tid / AK4;
    const int aC4 = (tid % AK4) * 4;

    for (; k0 < kend; k0 += BK) {
        // ---- load A tile (BM x BK), store transposed As[k][m]
        {
            float4 av = *(const float4*)&A[(m0 + aRow) * lda + k0 + aC4];
            As[(aC4 + 0) * BM + aRow] = av.x;
            As[(aC4 + 1) * BM + aRow] = av.y;
            As[(aC4 + 2) * BM + aRow] = av.z;
            As[(aC4 + 3) * BM + aRow] = av.w;
        }
        // ---- load B tile
        if (NN_MODE) {
            constexpr int BN4 = BN / 4;
            const int bK = tid / BN4;
            const int bC = (tid % BN4) * 4;
            float4 bv = *(const float4*)&Bm[(k0 + bK) * ldb + n0 + bC];
            *(float4*)&Bs[bK * BN + bC] = bv;
        } else {
            const int bRow = tid / AK4;
            const int bC4 = (tid % AK4) * 4;
            float4 bv = *(const float4*)&Bm[(n0 + bRow) * ldb + k0 + bC4];
            Bs[(bC4 + 0) * BN + bRow] = bv.x;
            Bs[(bC4 + 1) * BN + bRow] = bv.y;
            Bs[(bC4 + 2) * BN + bRow] = bv.z;
            Bs[(bC4 + 3) * BN + bRow] = bv.w;
        }
        __syncthreads();

#pragma unroll
        for (int k = 0; k < BK; k++) {
            float ar[TM], br[TN];
#pragma unroll
            for (int i = 0; i < TM; i += 4)
                *(float4*)&ar[i] = *(const float4*)&As[k * BM + ty * TM + i];
#pragma unroll
            for (int j = 0; j < TN; j += 4)
                *(float4*)&br[j] = *(const float4*)&Bs[k * BN + tx * TN + j];
#pragma unroll
            for (int i = 0; i < TM; i++)
#pragma unroll
                for (int j = 0; j < TN; j++) acc[i][j] = fmaf(ar[i], br[j], acc[i][j]);
        }
        __syncthreads();
    }

    // ---- epilogue
#pragma unroll
    for (int i = 0; i < TM; i++) {
        const int r = m0 + ty * TM + i;
#pragma unroll
        for (int j = 0; j < TN; j++) {
            const int c = n0 + tx * TN + j;
            float v = acc[i][j] * alpha;
            if (ATOMIC) {
                atomicAdd(&C[r * ldc + c], v);
            } else {
                if (bias) v += bias[c];
                if (act == 1) v = fmaxf(v, 0.0f);
                else if (act == 2) v = 1.0f / (1.0f + expf(-v));
                if (mul) v *= mul[r * ldc + c];
                C[r * ldc + c] = v;
            }
        }
    }
}

// ---------------- small helper kernels -------------------------------------
// out[row] = b2[row] + dot(W[row,:], b1)   (rows = Dd)
__global__ void bias_combine_k(const float* __restrict__ W, const float* __restrict__ b1,
                               const float* __restrict__ b2, float* __restrict__ out)
{
    const int row = blockIdx.x * blockDim.y + threadIdx.y;
    const int lane = threadIdx.x;
    float s = 0.0f;
    for (int c = lane; c < Dd; c += 32) s += W[row * Dd + c] * b1[c];
#pragma unroll
    for (int o = 16; o; o >>= 1) s += __shfl_down_sync(0xffffffffu, s, o);
    if (lane == 0) out[row] = s + b2[row];
}

__global__ void zero_k(float* p, int n)
{
    const int i = blockIdx.x * 256 + threadIdx.x;
    if (i < n) p[i] = 0.0f;
}

// o[B x 2D] = concat(a[B x D], b[B x D])
__global__ void concat_k(const float* __restrict__ a, const float* __restrict__ b,
                         float* __restrict__ o)
{
    const int i = blockIdx.x * 256 + threadIdx.x;
    if (i >= Bb * 2 * Dd) return;
    const int r = i / (2 * Dd);
    const int c = i % (2 * Dd);
    o[i] = (c < Dd) ? a[r * Dd + c] : b[r * Dd + c - Dd];
}

// in-place softmax over rows of length Mm; grid = B*H rows
__global__ void softmax_k(float* __restrict__ s)
{
    float* row = s + (size_t)blockIdx.x * Mm;
    __shared__ float red[256];
    const int t = threadIdx.x;

    float mx = -1e30f;
    for (int i = t; i < Mm; i += 256) mx = fmaxf(mx, row[i]);
    red[t] = mx;
    __syncthreads();
    for (int o = 128; o; o >>= 1) {
        if (t < o) red[t] = fmaxf(red[t], red[t + o]);
        __syncthreads();
    }
    mx = red[0];
    __syncthreads();

    float sum = 0.0f;
    for (int i = t; i < Mm; i += 256) {
        float e = expf(row[i] - mx);
        row[i] = e;
        sum += e;
    }
    red[t] = sum;
    __syncthreads();
    for (int o = 128; o; o >>= 1) {
        if (t < o) red[t] += red[t + o];
        __syncthreads();
    }
    const float inv = 1.0f / red[0];
    for (int i = t; i < Mm; i += 256) row[i] *= inv;
}

// ---------------- launch ----------------------------------------------------
extern "C" void kernel_launch(void* const* d_in, const int* in_sizes, int n_in,
                              void* d_out, int out_size)
{
    (void)in_sizes; (void)n_in; (void)out_size;
    const float* x    = (const float*)d_in[0];
    const float* mk   = (const float*)d_in[1];
    const float* mv   = (const float*)d_in[2];
    const float* Wq   = (const float*)d_in[3];
    const float* bq   = (const float*)d_in[4];
    const float* Wk   = (const float*)d_in[5];
    const float* bk   = (const float*)d_in[6];
    const float* Wv   = (const float*)d_in[7];
    const float* bv   = (const float*)d_in[8];
    const float* ipw  = (const float*)d_in[9];   // (3D, D)
    const float* ipb  = (const float*)d_in[10];  // (3D,)
    const float* outw = (const float*)d_in[11];
    const float* outb = (const float*)d_in[12];
    const float* gW1  = (const float*)d_in[13];  // (D, 2D)
    const float* gb1  = (const float*)d_in[14];
    const float* gW2  = (const float*)d_in[15];
    const float* gb2  = (const float*)d_in[16];
    const float* iW1  = (const float*)d_in[17];  // (2D, 2D)
    const float* ib1  = (const float*)d_in[18];
    const float* iW2  = (const float*)d_in[19];  // (D, 2D)
    const float* ib2  = (const float*)d_in[20];
    float* out = (float*)d_out;

    const float* Wiq = ipw;
    const float* Wik = ipw + Dd * Dd;
    const float* Wiv = ipw + 2 * Dd * Dd;
    const float* biq = ipb;
    const float* bik = ipb + Dd;
    const float* biv = ipb + 2 * Dd;

    // resolve device-global addresses (host side; not an allocation)
    float *q, *qh, *Wck, *Wcv, *bck, *bcv, *kh, *vh, *scores, *ctx, *ms, *gin, *g1, *gated, *comb, *i1;
    cudaGetSymbolAddress((void**)&q, g_q);
    cudaGetSymbolAddress((void**)&qh, g_qh);
    cudaGetSymbolAddress((void**)&Wck, g_Wck);
    cudaGetSymbolAddress((void**)&Wcv, g_Wcv);
    cudaGetSymbolAddress((void**)&bck, g_bck);
    cudaGetSymbolAddress((void**)&bcv, g_bcv);
    cudaGetSymbolAddress((void**)&kh, g_kh);
    cudaGetSymbolAddress((void**)&vh, g_vh);
    cudaGetSymbolAddress((void**)&scores, g_scores);
    cudaGetSymbolAddress((void**)&ctx, g_ctx);
    cudaGetSymbolAddress((void**)&ms, g_ms);
    cudaGetSymbolAddress((void**)&gin, g_gin);
    cudaGetSymbolAddress((void**)&g1, g_g1);
    cudaGetSymbolAddress((void**)&gated, g_gated);
    cudaGetSymbolAddress((void**)&comb, g_comb);
    cudaGetSymbolAddress((void**)&i1, g_i1);

    const dim3 blk(256);

    // 1) combined biases: bck = bik + Wik@bk ; bcv = biv + Wiv@bv
    bias_combine_k<<<Dd / 8, dim3(32, 8)>>>(Wik, bk, bik, bck);
    bias_combine_k<<<Dd / 8, dim3(32, 8)>>>(Wiv, bv, biv, bcv);

    // 2) combined weights: Wck = Wik @ Wk, Wcv = Wiv @ Wv   (NN, 1024^3)
    gemm_k<128, 128, 8, 8, 8, true, false><<<dim3(8, 8, 1), blk>>>(
        Wik, Wk, Wck, Dd, Dd, Dd, Dd, Dd, Dd, 0, 0, 0, 1, 1.0f, nullptr, 0, nullptr);
    gemm_k<128, 128, 8, 8, 8, true, false><<<dim3(8, 8, 1), blk>>>(
        Wiv, Wv, Wcv, Dd, Dd, Dd, Dd, Dd, Dd, 0, 0, 0, 1, 1.0f, nullptr, 0, nullptr);

    // 3) kh = keys @ Wck^T + bck ; vh = values @ Wcv^T + bcv   (TN, 8192x1024x1024)
    gemm_k<128, 128, 8, 8, 8, false, false><<<dim3(8, 64, 1), blk>>>(
        mk, Wck, kh, Mm, Dd, Dd, Dd, Dd, Dd, 0, 0, 0, 1, 1.0f, bck, 0, nullptr);
    gemm_k<128, 128, 8, 8, 8, false, false><<<dim3(8, 64, 1), blk>>>(
        mv, Wcv, vh, Mm, Dd, Dd, Dd, Dd, Dd, 0, 0, 0, 1, 1.0f, bcv, 0, nullptr);

    // 4) q = x @ Wq^T + bq ; qh = q @ Wiq^T + biq   (TN small)
    gemm_k<64, 64, 16, 4, 4, false, false><<<dim3(16, 1, 1), blk>>>(
        x, Wq, q, Bb, Dd, Dd, Dd, Dd, Dd, 0, 0, 0, 1, 1.0f, bq, 0, nullptr);
    gemm_k<64, 64, 16, 4, 4, false, false><<<dim3(16, 1, 1), blk>>>(
        q, Wiq, qh, Bb, Dd, Dd, Dd, Dd, Dd, 0, 0, 0, 1, 1.0f, biq, 0, nullptr);

    // 5) scores[b,h,m] = 0.125 * sum_d qh[b,h*64+d]*kh[m,h*64+d]   (batched TN per head)
    gemm_k<64, 64, 16, 4, 4, false, false><<<dim3(Mm / 64, 1, Hh), blk>>>(
        qh, kh, scores, Bb, Mm, HDd, Dd, Dd, Hh * Mm, HDd, HDd, Mm,
        1, 0.125f, nullptr, 0, nullptr);

    // 6) softmax over m
    softmax_k<<<Bb * Hh, blk>>>(scores);

    // 7) ctx = attn @ vh   (batched NN per head, split-K=8, atomic accumulate)
    zero_k<<<(Bb * Dd + 255) / 256, blk>>>(ctx, Bb * Dd);
    gemm_k<64, 64, 16, 4, 4, true, true><<<dim3(1, 1, Hh * 8), blk>>>(
        scores, vh, ctx, Bb, HDd, Mm, Hh * Mm, Dd, Dd, Mm, HDd, HDd,
        8, 1.0f, nullptr, 0, nullptr);

    // 8) memory_signal = ctx @ out_w^T + out_b
    gemm_k<64, 64, 16, 4, 4, false, false><<<dim3(16, 1, 1), blk>>>(
        ctx, outw, ms, Bb, Dd, Dd, Dd, Dd, Dd, 0, 0, 0, 1, 1.0f, outb, 0, nullptr);

    // 9) gate path: gin = [x, ms]; g1 = relu(gin@gW1^T+gb1); gated = sigmoid(g1@gW2^T+gb2)*ms
    concat_k<<<(Bb * 2 * Dd + 255) / 256, blk>>>(x, ms, gin);
    gemm_k<64, 64, 16, 4, 4, false, false><<<dim3(16, 1, 1), blk>>>(
        gin, gW1, g1, Bb, Dd, 2 * Dd, 2 * Dd, 2 * Dd, Dd, 0, 0, 0, 1, 1.0f, gb1, 1, nullptr);
    gemm_k<64, 64, 16, 4, 4, false, false><<<dim3(16, 1, 1), blk>>>(
        g1, gW2, gated, Bb, Dd, Dd, Dd, Dd, Dd, 0, 0, 0, 1, 1.0f, gb2, 2, ms);

    // 10) output path: comb = [x, gated]; i1 = relu(comb@iW1^T+ib1); out = i1@iW2^T+ib2
    concat_k<<<(Bb * 2 * Dd + 255) / 256, blk>>>(x, gated, comb);
    gemm_k<64, 64, 16, 4, 4, false, false><<<dim3(32, 1, 1), blk>>>(
        comb, iW1, i1, Bb, 2 * Dd, 2 * Dd, 2 * Dd, 2 * Dd, 2 * Dd, 0, 0, 0, 1, 1.0f, ib1, 1, nullptr);
    gemm_k<64, 64, 16, 4, 4, false, false><<<dim3(16, 1, 1), blk>>>(
        i1, iW2, out, Bb, Dd, 2 * Dd, 2 * Dd, 2 * Dd, Dd, 0, 0, 0, 1, 1.0f, ib2, 0, nullptr);
}